// round 14
// baseline (speedup 1.0000x reference)
#include <cuda_runtime.h>
#include <cstdint>

// ---------------------------------------------------------------------------
// QuadTreeDecoder round 14 — TWO launches.
//  qt_prep: WF5 + WFA + G per level-5 node (unchanged, validated R13)
//  qt_mega: per (p4, batch-quarter): recompute path l0..l3 in smem columns,
//           then stack [fi4s|fi5s x4|W].x4 -> smem, then final (lat-space)
//           per level-5 child -> pixels. No intermediate gmem activations.
// ---------------------------------------------------------------------------

typedef unsigned long long u64;

__device__ float g_wf[(size_t)1024 * 4 * 48 * 16];   // WF5[cn][c][48][16]
__device__ float g_wfa[(size_t)1024 * 48 * 16];      // WFA[cn][48][16]
__device__ float g_g[(size_t)1024 * 16 * 16];        // G[cn][16][16]

// ---------------------------------------------------------------------------
__device__ __forceinline__ void fma2(u64& d, u64 a, u64 b) {
    asm("fma.rn.f32x2 %0, %1, %2, %3;" : "=l"(d) : "l"(a), "l"(b), "l"(d));
}
__device__ __forceinline__ u64 pack2(float lo, float hi) {
    u64 r; asm("mov.b64 %0, {%1, %2};" : "=l"(r) : "f"(lo), "f"(hi)); return r;
}
__device__ __forceinline__ float fold2(u64 v) {
    float lo, hi; asm("mov.b64 {%0, %1}, %2;" : "=f"(lo), "=f"(hi) : "l"(v));
    return lo + hi;
}

// ---------------------------------------------------------------------------
__device__ __forceinline__ void stage_factor_n(float (*dst)[64], const float* __restrict__ src,
                                               const float* __restrict__ sc, int tid, int nthr)
{
    const float4* s4 = (const float4*)src;
    float4* d4 = (float4*)dst;
    if (sc) {
        for (int idx = tid; idx < 256; idx += nthr) {
            float4 v = s4[idx];
            float s = __ldg(&sc[idx >> 4]);
            v.x *= s; v.y *= s; v.z *= s; v.w *= s;
            d4[idx] = v;
        }
    } else {
        for (int idx = tid; idx < 256; idx += nthr)
            d4[idx] = s4[idx];
    }
}

// ---------------------------------------------------------------------------
// qt_prep (validated R13): per cn (1024 blocks x 256):
//   WF5[cn][c][k][r] = W[k]   . F5_c[341+cn][r]   (threads 0..191)
//   WFA[cn][k][r4]   = W[k]   . F4_c4[85+p4][r4]  (threads 192..239)
//   G  [cn][r][r4]   = fi5s[r]. F4_c4[85+p4][r4]  (threads 240..255)
// ---------------------------------------------------------------------------
__global__ __launch_bounds__(256)
void qt_prep(const float* __restrict__ ftl, const float* __restrict__ ftr,
             const float* __restrict__ fbl, const float* __restrict__ fbr,
             const float* __restrict__ fin, const float* __restrict__ scale,
             const float* __restrict__ head_w,
             float* __restrict__ wf, float* __restrict__ wfa, float* __restrict__ gg)
{
    __shared__ __align__(16) float F4s[16][64];
    __shared__ __align__(16) float fi5s[16][64];
    __shared__ __align__(16) float F5s[4][16][64];
    __shared__ __align__(16) float w_s[48][64];

    const int cn  = blockIdx.x;
    const int tid = threadIdx.x;
    const int r5 = cn >> 5, c5 = cn & 31;
    const int p4 = (r5 >> 1) * 16 + (c5 >> 1);
    const int c4 = ((r5 & 1) << 1) | (c5 & 1);
    const int nodeA = 85 + p4;
    const int nodeB = 341 + cn;

    const float* FcA = (c4 == 0 ? ftl : c4 == 1 ? ftr : c4 == 2 ? fbl : fbr)
                       + (size_t)nodeA * 1024;

    stage_factor_n(F4s, FcA, nullptr, tid, 256);
    stage_factor_n(fi5s, fin + (size_t)nodeB * 1024, scale + (size_t)nodeB * 16, tid, 256);
    stage_factor_n(F5s[0], ftl + (size_t)nodeB * 1024, nullptr, tid, 256);
    stage_factor_n(F5s[1], ftr + (size_t)nodeB * 1024, nullptr, tid, 256);
    stage_factor_n(F5s[2], fbl + (size_t)nodeB * 1024, nullptr, tid, 256);
    stage_factor_n(F5s[3], fbr + (size_t)nodeB * 1024, nullptr, tid, 256);
    {
        const float4* w4 = (const float4*)head_w;
        float4* d = (float4*)w_s;
        for (int i = tid; i < 768; i += 256) d[i] = w4[i];
    }
    __syncthreads();

    u64 acc[16];
#pragma unroll
    for (int r = 0; r < 16; r++) acc[r] = 0ull;

    if (tid < 192) {
        const int c = tid / 48;
        const int k = tid - c * 48;
#pragma unroll 4
        for (int i4 = 0; i4 < 16; i4++) {
            ulonglong2 wv = *(const ulonglong2*)&w_s[k][i4 * 4];
#pragma unroll
            for (int r = 0; r < 16; r++) {
                ulonglong2 f = *(const ulonglong2*)&F5s[c][r][i4 * 4];
                fma2(acc[r], wv.x, f.x);
                fma2(acc[r], wv.y, f.y);
            }
        }
        float* dst = wf + ((size_t)cn * 4 + c) * 768 + (size_t)k * 16;
#pragma unroll
        for (int r = 0; r < 16; r += 4)
            *(float4*)(dst + r) = make_float4(fold2(acc[r]), fold2(acc[r+1]),
                                              fold2(acc[r+2]), fold2(acc[r+3]));
    } else if (tid < 240) {
        const int k = tid - 192;
#pragma unroll 4
        for (int i4 = 0; i4 < 16; i4++) {
            ulonglong2 wv = *(const ulonglong2*)&w_s[k][i4 * 4];
#pragma unroll
            for (int r = 0; r < 16; r++) {
                ulonglong2 f = *(const ulonglong2*)&F4s[r][i4 * 4];
                fma2(acc[r], wv.x, f.x);
                fma2(acc[r], wv.y, f.y);
            }
        }
        float* dst = wfa + (size_t)cn * 768 + (size_t)k * 16;
#pragma unroll
        for (int r = 0; r < 16; r += 4)
            *(float4*)(dst + r) = make_float4(fold2(acc[r]), fold2(acc[r+1]),
                                              fold2(acc[r+2]), fold2(acc[r+3]));
    } else {
        const int r = tid - 240;
#pragma unroll 4
        for (int i4 = 0; i4 < 16; i4++) {
            ulonglong2 av = *(const ulonglong2*)&fi5s[r][i4 * 4];
#pragma unroll
            for (int r4 = 0; r4 < 16; r4++) {
                ulonglong2 f = *(const ulonglong2*)&F4s[r4][i4 * 4];
                fma2(acc[r4], av.x, f.x);
                fma2(acc[r4], av.y, f.y);
            }
        }
        float* dst = gg + (size_t)cn * 256 + (size_t)r * 16;
#pragma unroll
        for (int r4 = 0; r4 < 16; r4 += 4)
            *(float4*)(dst + r4) = make_float4(fold2(acc[r4]), fold2(acc[r4+1]),
                                               fold2(acc[r4+2]), fold2(acc[r4+3]));
    }
}

// ---------------------------------------------------------------------------
// transform: x_col += F^T (fi . x_col), r/o split by kq quarters (sync inside)
// ---------------------------------------------------------------------------
__device__ __forceinline__ void qt_transform(
    float4 (*x_s)[32], float (*lat_s)[32],
    const float (*__restrict__ fi)[64], const float (*__restrict__ F)[64],
    int col, int rq)
{
    {
        u64 a[4];
#pragma unroll
        for (int rr = 0; rr < 4; rr++) a[rr] = 0ull;
#pragma unroll 4
        for (int i4 = 0; i4 < 16; i4++) {
            ulonglong2 xv = *(const ulonglong2*)&x_s[i4][col];
#pragma unroll
            for (int rr = 0; rr < 4; rr++) {
                ulonglong2 f = *(const ulonglong2*)&fi[rq + rr][i4 * 4];
                fma2(a[rr], xv.x, f.x);
                fma2(a[rr], xv.y, f.y);
            }
        }
#pragma unroll
        for (int rr = 0; rr < 4; rr++) lat_s[rq + rr][col] = fold2(a[rr]);
    }
    __syncthreads();
    {
        u64 lp[16];
#pragma unroll
        for (int r = 0; r < 16; r++) {
            float v = lat_s[r][col];
            lp[r] = pack2(v, v);
        }
#pragma unroll
        for (int oo = 0; oo < 4; oo++) {
            const int o4 = rq + oo;
            ulonglong2 a = *(const ulonglong2*)&x_s[o4][col];
#pragma unroll
            for (int r = 0; r < 16; r++) {
                ulonglong2 f = *(const ulonglong2*)&F[r][o4 * 4];
                fma2(a.x, lp[r], f.x);
                fma2(a.y, lp[r], f.y);
            }
            *(ulonglong2*)&x_s[o4][col] = a;
        }
    }
    __syncthreads();
}

// ---------------------------------------------------------------------------
// qt_mega: grid 1024 (p4*4 + q4), 128 thr = kq(4) x col(32). Dynamic smem.
// ---------------------------------------------------------------------------
// smem layout (bytes):
//   [0      , 16384 ) pathF[4][16][64]  — l0/l1 then l2/l3 factors; phase B:
//                       wf5_s[192][16] (12288) | wfa_s[48][16] (3072) | g_s (1024)
//   [16384  , 49152 ) FI[128][64]       — fi4s | fi5s(cn0..3) | W
//   [49152  , 57344 ) x_s float4[16][32]
//   [57344  , 59392 ) lat_s[16][32]
//   [59392  , 61440 ) lat4_s[16][32]
//   [61440  , 69632 ) f5x_s[4][16][32]
//   [69632  , 75776 ) wx_s[48][32]
//   [75776  , 75968 ) hb_s[48]
#define MEGA_SMEM 76032

__global__ __launch_bounds__(128)
void qt_mega(const float* __restrict__ x0,
             const float* __restrict__ fin,
             const float* __restrict__ ftl, const float* __restrict__ ftr,
             const float* __restrict__ fbl, const float* __restrict__ fbr,
             const float* __restrict__ scale,
             const float* __restrict__ wf, const float* __restrict__ wfa,
             const float* __restrict__ gg,
             const float* __restrict__ head_w, const float* __restrict__ head_b,
             float* __restrict__ out)
{
    extern __shared__ __align__(16) char sm[];
    float (*pathF)[64]  = (float (*)[64])(sm);                 // 64 rows x 64
    float (*FI)[64]     = (float (*)[64])(sm + 16384);
    float4 (*x_s)[32]   = (float4 (*)[32])(sm + 49152);
    float (*lat_s)[32]  = (float (*)[32])(sm + 57344);
    float (*lat4_s)[32] = (float (*)[32])(sm + 59392);
    float (*f5x_s)[32]  = (float (*)[32])(sm + 61440);         // [4*16][32]
    float (*wx_s)[32]   = (float (*)[32])(sm + 69632);
    float* hb_s         = (float*)(sm + 75776);
    // phase-B aliases of pathF
    float (*wf5_s)[16]  = (float (*)[16])(sm);                 // [192][16]
    float (*wfa_s)[16]  = (float (*)[16])(sm + 12288);         // [48][16]
    float (*g_s)[16]    = (float (*)[16])(sm + 15360);         // [16][16]

    const int bid = blockIdx.x;
    const int p4  = bid >> 2;
    const int q4  = bid & 3;
    const int tid = threadIdx.x;
    const int col = tid & 31;
    const int kq  = tid >> 5;
    const int rq  = kq * 4;
    const int k0  = kq * 12;

    // ---- path indices: p4 -> p3 -> p2 -> p1 -> root
    const int r4 = p4 >> 4, k4 = p4 & 15;
    const int p3 = (r4 >> 1) * 8 + (k4 >> 1), c3 = ((r4 & 1) << 1) | (k4 & 1);
    const int r3 = p3 >> 3, k3 = p3 & 7;
    const int p2 = (r3 >> 1) * 4 + (k3 >> 1), c2 = ((r3 & 1) << 1) | (k3 & 1);
    const int r2 = p2 >> 2, k2 = p2 & 3;
    const int p1 = (r2 >> 1) * 2 + (k2 >> 1), c1 = ((r2 & 1) << 1) | (k2 & 1);
    const int c0 = p1;

    const int node1 = 1 + p1, node2 = 5 + p2, node3 = 21 + p3, node4 = 85 + p4;
    const int gr4 = p4 >> 4, gc4 = p4 & 15;

    // ---- stage FI (stack weights) + hb + x0 + path(l0,l1)
    stage_factor_n(&FI[0], fin + (size_t)node4 * 1024, scale + (size_t)node4 * 16, tid, 128);
#pragma unroll
    for (int j = 0; j < 4; j++) {
        const int cnj = (2 * gr4 + (j >> 1)) * 32 + 2 * gc4 + (j & 1);
        const int node5 = 341 + cnj;
        stage_factor_n(&FI[16 + 16 * j], fin + (size_t)node5 * 1024,
                       scale + (size_t)node5 * 16, tid, 128);
    }
    {
        const float4* w4 = (const float4*)head_w;
        float4* d = (float4*)&FI[80][0];
        for (int i = tid; i < 768; i += 128) d[i] = w4[i];
        if (tid < 48) hb_s[tid] = head_b[tid];
        // x0 b-major: 512 float4 per block, coalesced
        const float4* x04 = (const float4*)x0;
#pragma unroll
        for (int j = 0; j < 4; j++) {
            int idx = tid + j * 128;          // b_loc*16 + i4
            int bl = idx >> 4, i4 = idx & 15;
            x_s[i4][bl] = x04[(size_t)(q4 * 32 + bl) * 16 + i4];
        }
    }
    const float* F0 = (c0 == 0 ? ftl : c0 == 1 ? ftr : c0 == 2 ? fbl : fbr);
    const float* F1 = (c1 == 0 ? ftl : c1 == 1 ? ftr : c1 == 2 ? fbl : fbr)
                      + (size_t)node1 * 1024;
    stage_factor_n(&pathF[0],  fin, scale, tid, 128);
    stage_factor_n(&pathF[16], F0, nullptr, tid, 128);
    stage_factor_n(&pathF[32], fin + (size_t)node1 * 1024, scale + (size_t)node1 * 16, tid, 128);
    stage_factor_n(&pathF[48], F1, nullptr, tid, 128);
    __syncthreads();

    // ---- levels 0, 1
    qt_transform(x_s, lat_s, &pathF[0],  &pathF[16], col, rq);
    qt_transform(x_s, lat_s, &pathF[32], &pathF[48], col, rq);

    // ---- restage path(l2,l3)  (previous transform ended with sync)
    {
        const float* F2 = (c2 == 0 ? ftl : c2 == 1 ? ftr : c2 == 2 ? fbl : fbr)
                          + (size_t)node2 * 1024;
        const float* F3 = (c3 == 0 ? ftl : c3 == 1 ? ftr : c3 == 2 ? fbl : fbr)
                          + (size_t)node3 * 1024;
        stage_factor_n(&pathF[0],  fin + (size_t)node2 * 1024, scale + (size_t)node2 * 16, tid, 128);
        stage_factor_n(&pathF[16], F2, nullptr, tid, 128);
        stage_factor_n(&pathF[32], fin + (size_t)node3 * 1024, scale + (size_t)node3 * 16, tid, 128);
        stage_factor_n(&pathF[48], F3, nullptr, tid, 128);
    }
    __syncthreads();

    // ---- levels 2, 3   (x_s becomes x4)
    qt_transform(x_s, lat_s, &pathF[0],  &pathF[16], col, rq);
    qt_transform(x_s, lat_s, &pathF[32], &pathF[48], col, rq);

    // ---- stack: [fi4s | fi5s(4) | W] . x4 -> lat4_s / f5x_s / wx_s
#pragma unroll 1
    for (int half = 0; half < 2; half++) {
        const int g = kq * 2 + half;        // 0..7
        const int rbase = g * 16;

        u64 acc[16];
#pragma unroll
        for (int rr = 0; rr < 16; rr++) acc[rr] = 0ull;
#pragma unroll 2
        for (int i4 = 0; i4 < 16; i4++) {
            ulonglong2 xv = *(const ulonglong2*)&x_s[i4][col];
#pragma unroll
            for (int rr = 0; rr < 16; rr++) {
                ulonglong2 f = *(const ulonglong2*)&FI[rbase + rr][i4 * 4];
                fma2(acc[rr], xv.x, f.x);
                fma2(acc[rr], xv.y, f.y);
            }
        }

        if (g == 0) {
#pragma unroll
            for (int rr = 0; rr < 16; rr++) lat4_s[rr][col] = fold2(acc[rr]);
        } else if (g <= 4) {
            const int j = g - 1;
#pragma unroll
            for (int rr = 0; rr < 16; rr++) f5x_s[j * 16 + rr][col] = fold2(acc[rr]);
        } else {
            const int kk0 = (g - 5) * 16;
#pragma unroll
            for (int rr = 0; rr < 16; rr++)
                wx_s[kk0 + rr][col] = fold2(acc[rr]) + hb_s[kk0 + rr];
        }
    }
    __syncthreads();

    // ---- lat4 packed (own col)
    u64 latq4[8];
#pragma unroll
    for (int j = 0; j < 8; j++)
        latq4[j] = pack2(lat4_s[2*j][col], lat4_s[2*j + 1][col]);

    const int b = q4 * 32 + col;

    // ---- final: loop over 4 level-5 children
#pragma unroll 1
    for (int j = 0; j < 4; j++) {
        if (j) __syncthreads();             // previous child's weight reads done
        const int cn = (2 * gr4 + (j >> 1)) * 32 + 2 * gc4 + (j & 1);

        // stage WF5 / WFA / G into pathF alias region
        {
            const float4* s5 = (const float4*)(wf + (size_t)cn * 3072);
            float4* d5 = (float4*)wf5_s;
            for (int i = tid; i < 768; i += 128) d5[i] = s5[i];
            const float4* sa = (const float4*)(wfa + (size_t)cn * 768);
            float4* da = (float4*)wfa_s;
            for (int i = tid; i < 192; i += 128) da[i] = sa[i];
            if (tid < 64)
                ((float4*)g_s)[tid] = ((const float4*)(gg + (size_t)cn * 256))[tid];
        }
        __syncthreads();

        // lat5 = F5X + G.lat4
        float l5[16];
#pragma unroll
        for (int r = 0; r < 16; r++) {
            const ulonglong2* grow = (const ulonglong2*)&g_s[r][0];
            u64 a = 0ull;
#pragma unroll
            for (int jj = 0; jj < 4; jj++) {
                ulonglong2 f = grow[jj];
                fma2(a, latq4[2*jj],     f.x);
                fma2(a, latq4[2*jj + 1], f.y);
            }
            l5[r] = f5x_s[j * 16 + r][col] + fold2(a);
        }
        u64 latq5[8];
#pragma unroll
        for (int jj = 0; jj < 8; jj++) latq5[jj] = pack2(l5[2*jj], l5[2*jj + 1]);

        // tk = WX + WFA.lat4 (own 12 k's)
        float tk[12];
#pragma unroll
        for (int kk = 0; kk < 12; kk++) {
            const ulonglong2* ar = (const ulonglong2*)&wfa_s[k0 + kk][0];
            u64 a = 0ull;
#pragma unroll
            for (int jj = 0; jj < 4; jj++) {
                ulonglong2 f = ar[jj];
                fma2(a, latq4[2*jj],     f.x);
                fma2(a, latq4[2*jj + 1], f.y);
            }
            tk[kk] = wx_s[k0 + kk][col] + fold2(a);
        }

        // 4 grandchildren -> pixels
        const int r5 = cn >> 5, c5 = cn & 31;
#pragma unroll 1
        for (int c = 0; c < 4; c++) {
            const int cn6 = (2 * r5 + (c >> 1)) * 64 + 2 * c5 + (c & 1);

            float acc[12];
#pragma unroll
            for (int kk = 0; kk < 12; kk++) {
                const ulonglong2* wfr = (const ulonglong2*)&wf5_s[c * 48 + k0 + kk][0];
                u64 a = 0ull;
#pragma unroll
                for (int jj = 0; jj < 4; jj++) {
                    ulonglong2 f = wfr[jj];
                    fma2(a, latq5[2*jj],     f.x);
                    fma2(a, latq5[2*jj + 1], f.y);
                }
                acc[kk] = tk[kk] + fold2(a);
            }

            // k = kq*12 + pc*3 + oc  ->  pr == kq
            const int sr = cn6 >> 6, sc = cn6 & 63;
#pragma unroll
            for (int oc = 0; oc < 3; oc++) {
                float4 v = make_float4(acc[0 + oc], acc[3 + oc], acc[6 + oc], acc[9 + oc]);
                size_t row = (size_t)(b * 3 + oc) * 256 + (sr * 4 + kq);
                *(float4*)(out + row * 256 + sc * 4) = v;
            }
        }
    }
}

// ---------------------------------------------------------------------------
extern "C" void kernel_launch(void* const* d_in, const int* in_sizes, int n_in,
                              void* d_out, int out_size)
{
    const float* x      = (const float*)d_in[0];
    const float* fin    = (const float*)d_in[1];
    const float* ftl    = (const float*)d_in[2];
    const float* ftr    = (const float*)d_in[3];
    const float* fbl    = (const float*)d_in[4];
    const float* fbr    = (const float*)d_in[5];
    const float* scale  = (const float*)d_in[6];
    const float* head_w = (const float*)d_in[7];
    const float* head_b = (const float*)d_in[8];
    float* out = (float*)d_out;

    float *wfb, *wfab, *ggb;
    cudaGetSymbolAddress((void**)&wfb,  g_wf);
    cudaGetSymbolAddress((void**)&wfab, g_wfa);
    cudaGetSymbolAddress((void**)&ggb,  g_g);

    cudaFuncSetAttribute(qt_mega, cudaFuncAttributeMaxDynamicSharedMemorySize,
                         MEGA_SMEM);

    qt_prep<<<1024, 256>>>(ftl, ftr, fbl, fbr, fin, scale, head_w, wfb, wfab, ggb);
    qt_mega<<<1024, 128, MEGA_SMEM>>>(x, fin, ftl, ftr, fbl, fbr, scale,
                                      wfb, wfab, ggb, head_w, head_b, out);
}

// round 15
// speedup vs baseline: 1.3926x; 1.3926x over previous
#include <cuda_runtime.h>
#include <cstdint>

// ---------------------------------------------------------------------------
// QuadTreeDecoder round 15
//  R13 structure; qt_stack single-pass 256-thr; qt_final one block per cn
//  (weights staged once, batch-halves looped inside), 256 thr.
// ---------------------------------------------------------------------------

typedef unsigned long long u64;

__device__ float4 g_x2[(size_t)16  * 16 * 128];
__device__ float4 g_x4[(size_t)256 * 16 * 128];
__device__ float  g_wf[(size_t)1024 * 4 * 48 * 16];   // WF5[cn][c][48][16]
__device__ float  g_wfa[(size_t)1024 * 48 * 16];      // WFA[cn][48][16]
__device__ float  g_g[(size_t)1024 * 16 * 16];        // G[cn][16][16]
__device__ float  g_lat4[(size_t)256 * 16 * 128];     // LAT4[p4][r][b]
__device__ float  g_f5x[(size_t)1024 * 16 * 128];     // F5X[cn][r][b]
__device__ float  g_wx[(size_t)256 * 48 * 128];       // WX[p4][k][b]

// ---------------------------------------------------------------------------
__device__ __forceinline__ void fma2(u64& d, u64 a, u64 b) {
    asm("fma.rn.f32x2 %0, %1, %2, %3;" : "=l"(d) : "l"(a), "l"(b), "l"(d));
}
__device__ __forceinline__ u64 pack2(float lo, float hi) {
    u64 r; asm("mov.b64 %0, {%1, %2};" : "=l"(r) : "f"(lo), "f"(hi)); return r;
}
__device__ __forceinline__ float fold2(u64 v) {
    float lo, hi; asm("mov.b64 {%0, %1}, %2;" : "=f"(lo), "=f"(hi) : "l"(v));
    return lo + hi;
}

// ---------------------------------------------------------------------------
__device__ __forceinline__ void stage_factor_n(float (*dst)[64], const float* __restrict__ src,
                                               const float* __restrict__ sc, int tid, int nthr)
{
    const float4* s4 = (const float4*)src;
    float4* d4 = (float4*)dst;
    if (sc) {
        for (int idx = tid; idx < 256; idx += nthr) {
            float4 v = s4[idx];
            float s = __ldg(&sc[idx >> 4]);
            v.x *= s; v.y *= s; v.z *= s; v.w *= s;
            d4[idx] = v;
        }
    } else {
        for (int idx = tid; idx < 256; idx += nthr)
            d4[idx] = s4[idx];
    }
}

// ---------------------------------------------------------------------------
// qt_prep (validated): per cn (1024 blocks x 256):
//   WF5[cn][c][k][r], WFA[cn][k][r4], G[cn][r][r4]
// ---------------------------------------------------------------------------
__global__ __launch_bounds__(256)
void qt_prep(const float* __restrict__ ftl, const float* __restrict__ ftr,
             const float* __restrict__ fbl, const float* __restrict__ fbr,
             const float* __restrict__ fin, const float* __restrict__ scale,
             const float* __restrict__ head_w,
             float* __restrict__ wf, float* __restrict__ wfa, float* __restrict__ gg)
{
    __shared__ __align__(16) float F4s[16][64];
    __shared__ __align__(16) float fi5s[16][64];
    __shared__ __align__(16) float F5s[4][16][64];
    __shared__ __align__(16) float w_s[48][64];

    const int cn  = blockIdx.x;
    const int tid = threadIdx.x;
    const int r5 = cn >> 5, c5 = cn & 31;
    const int p4 = (r5 >> 1) * 16 + (c5 >> 1);
    const int c4 = ((r5 & 1) << 1) | (c5 & 1);
    const int nodeA = 85 + p4;
    const int nodeB = 341 + cn;

    const float* FcA = (c4 == 0 ? ftl : c4 == 1 ? ftr : c4 == 2 ? fbl : fbr)
                       + (size_t)nodeA * 1024;

    stage_factor_n(F4s, FcA, nullptr, tid, 256);
    stage_factor_n(fi5s, fin + (size_t)nodeB * 1024, scale + (size_t)nodeB * 16, tid, 256);
    stage_factor_n(F5s[0], ftl + (size_t)nodeB * 1024, nullptr, tid, 256);
    stage_factor_n(F5s[1], ftr + (size_t)nodeB * 1024, nullptr, tid, 256);
    stage_factor_n(F5s[2], fbl + (size_t)nodeB * 1024, nullptr, tid, 256);
    stage_factor_n(F5s[3], fbr + (size_t)nodeB * 1024, nullptr, tid, 256);
    {
        const float4* w4 = (const float4*)head_w;
        float4* d = (float4*)w_s;
        for (int i = tid; i < 768; i += 256) d[i] = w4[i];
    }
    __syncthreads();

    u64 acc[16];
#pragma unroll
    for (int r = 0; r < 16; r++) acc[r] = 0ull;

    if (tid < 192) {
        const int c = tid / 48;
        const int k = tid - c * 48;
#pragma unroll 4
        for (int i4 = 0; i4 < 16; i4++) {
            ulonglong2 wv = *(const ulonglong2*)&w_s[k][i4 * 4];
#pragma unroll
            for (int r = 0; r < 16; r++) {
                ulonglong2 f = *(const ulonglong2*)&F5s[c][r][i4 * 4];
                fma2(acc[r], wv.x, f.x);
                fma2(acc[r], wv.y, f.y);
            }
        }
        float* dst = wf + ((size_t)cn * 4 + c) * 768 + (size_t)k * 16;
#pragma unroll
        for (int r = 0; r < 16; r += 4)
            *(float4*)(dst + r) = make_float4(fold2(acc[r]), fold2(acc[r+1]),
                                              fold2(acc[r+2]), fold2(acc[r+3]));
    } else if (tid < 240) {
        const int k = tid - 192;
#pragma unroll 4
        for (int i4 = 0; i4 < 16; i4++) {
            ulonglong2 wv = *(const ulonglong2*)&w_s[k][i4 * 4];
#pragma unroll
            for (int r = 0; r < 16; r++) {
                ulonglong2 f = *(const ulonglong2*)&F4s[r][i4 * 4];
                fma2(acc[r], wv.x, f.x);
                fma2(acc[r], wv.y, f.y);
            }
        }
        float* dst = wfa + (size_t)cn * 768 + (size_t)k * 16;
#pragma unroll
        for (int r = 0; r < 16; r += 4)
            *(float4*)(dst + r) = make_float4(fold2(acc[r]), fold2(acc[r+1]),
                                              fold2(acc[r+2]), fold2(acc[r+3]));
    } else {
        const int r = tid - 240;
#pragma unroll 4
        for (int i4 = 0; i4 < 16; i4++) {
            ulonglong2 av = *(const ulonglong2*)&fi5s[r][i4 * 4];
#pragma unroll
            for (int r4 = 0; r4 < 16; r4++) {
                ulonglong2 f = *(const ulonglong2*)&F4s[r4][i4 * 4];
                fma2(acc[r4], av.x, f.x);
                fma2(acc[r4], av.y, f.y);
            }
        }
        float* dst = gg + (size_t)cn * 256 + (size_t)r * 16;
#pragma unroll
        for (int r4 = 0; r4 < 16; r4 += 4)
            *(float4*)(dst + r4) = make_float4(fold2(acc[r4]), fold2(acc[r4+1]),
                                               fold2(acc[r4+2]), fold2(acc[r4+3]));
    }
}

// ---------------------------------------------------------------------------
// Levels 0+1 fused, oh-split (R13, validated). 32 blocks x 128.
// ---------------------------------------------------------------------------
__global__ __launch_bounds__(128)
void qt_l01(const float* __restrict__ x0, float4* __restrict__ xout,
            const float* __restrict__ fin,
            const float* __restrict__ ftl, const float* __restrict__ ftr,
            const float* __restrict__ fbl, const float* __restrict__ fbr,
            const float* __restrict__ scale)
{
    __shared__ __align__(16) float fiA[16][64], FA[16][64], fiB[16][64], FB[16][64];
    __shared__ __align__(16) float4 x_s[16][64];
    __shared__ float lat_s[16][64];

    const int bid = blockIdx.x;
    const int p1  = bid >> 3;
    const int c1  = (bid >> 1) & 3;
    const int qh  = bid & 1;
    const int tid = threadIdx.x;
    const int col = tid & 63;
    const int oh  = tid >> 6;
    const int rb  = oh * 8;

    const float* FcA = (p1 == 0 ? ftl : p1 == 1 ? ftr : p1 == 2 ? fbl : fbr);
    const int nodeB = 1 + p1;
    const float* FcB = (c1 == 0 ? ftl : c1 == 1 ? ftr : c1 == 2 ? fbl : fbr)
                       + (size_t)nodeB * 1024;

    stage_factor_n(fiA, fin, scale, tid, 128);
    stage_factor_n(FA,  FcA, nullptr, tid, 128);
    stage_factor_n(fiB, fin + (size_t)nodeB * 1024, scale + (size_t)nodeB * 16, tid, 128);
    stage_factor_n(FB,  FcB, nullptr, tid, 128);
    {
#pragma unroll
        for (int j = 0; j < 8; j++) {
            int idx = tid + j * 128;
            int i4 = idx >> 6, c = idx & 63;
            x_s[i4][c] = ((const float4*)(x0 + (size_t)(qh * 64 + c) * 64))[i4];
        }
    }
    __syncthreads();

    u64 lp[16];

    {   // latA r-half
        u64 a[8];
#pragma unroll
        for (int rr = 0; rr < 8; rr++) a[rr] = 0ull;
#pragma unroll 4
        for (int i4 = 0; i4 < 16; i4++) {
            ulonglong2 xv = *(const ulonglong2*)&x_s[i4][col];
#pragma unroll
            for (int rr = 0; rr < 8; rr++) {
                ulonglong2 f = *(const ulonglong2*)&fiA[rb + rr][i4 * 4];
                fma2(a[rr], xv.x, f.x);
                fma2(a[rr], xv.y, f.y);
            }
        }
#pragma unroll
        for (int rr = 0; rr < 8; rr++) lat_s[rb + rr][col] = fold2(a[rr]);
    }
    __syncthreads();

#pragma unroll
    for (int r = 0; r < 16; r++) { float v = lat_s[r][col]; lp[r] = pack2(v, v); }
#pragma unroll 4
    for (int oo = 0; oo < 8; oo++) {
        const int o4 = rb + oo;
        ulonglong2 a = *(const ulonglong2*)&x_s[o4][col];
#pragma unroll
        for (int r = 0; r < 16; r++) {
            ulonglong2 f = *(const ulonglong2*)&FA[r][o4 * 4];
            fma2(a.x, lp[r], f.x);
            fma2(a.y, lp[r], f.y);
        }
        *(ulonglong2*)&x_s[o4][col] = a;
    }
    __syncthreads();

    {   // latB r-half
        u64 a[8];
#pragma unroll
        for (int rr = 0; rr < 8; rr++) a[rr] = 0ull;
#pragma unroll 4
        for (int i4 = 0; i4 < 16; i4++) {
            ulonglong2 xv = *(const ulonglong2*)&x_s[i4][col];
#pragma unroll
            for (int rr = 0; rr < 8; rr++) {
                ulonglong2 f = *(const ulonglong2*)&fiB[rb + rr][i4 * 4];
                fma2(a[rr], xv.x, f.x);
                fma2(a[rr], xv.y, f.y);
            }
        }
#pragma unroll
        for (int rr = 0; rr < 8; rr++) lat_s[rb + rr][col] = fold2(a[rr]);
    }
    __syncthreads();

#pragma unroll
    for (int r = 0; r < 16; r++) { float v = lat_s[r][col]; lp[r] = pack2(v, v); }
    const int gr = p1 >> 1, gc = p1 & 1;
    const int cn = (2 * gr + (c1 >> 1)) * 4 + 2 * gc + (c1 & 1);
    float4* op = xout + ((size_t)cn * 16) * 128 + qh * 64 + col;
#pragma unroll 4
    for (int oo = 0; oo < 8; oo++) {
        const int o4 = rb + oo;
        ulonglong2 a = *(const ulonglong2*)&x_s[o4][col];
#pragma unroll
        for (int r = 0; r < 16; r++) {
            ulonglong2 f = *(const ulonglong2*)&FB[r][o4 * 4];
            fma2(a.x, lp[r], f.x);
            fma2(a.y, lp[r], f.y);
        }
        *(ulonglong2*)&op[o4 * 128] = a;
    }
}

// ---------------------------------------------------------------------------
// Levels 2+3 fused, oh-split (R13, validated). 512 blocks x 128.
// ---------------------------------------------------------------------------
__global__ __launch_bounds__(128)
void qt_l23(const float4* __restrict__ xin, float4* __restrict__ xout,
            const float* __restrict__ fin,
            const float* __restrict__ ftl, const float* __restrict__ ftr,
            const float* __restrict__ fbl, const float* __restrict__ fbr,
            const float* __restrict__ scale)
{
    __shared__ __align__(16) float fiA[16][64], FA[16][64], fiB[16][64], FB[16][64];
    __shared__ __align__(16) float4 x_s[16][64];
    __shared__ float lat_s[16][64];

    const int bid = blockIdx.x;
    const int p3  = bid >> 3;
    const int c3  = (bid >> 1) & 3;
    const int qh  = bid & 1;
    const int tid = threadIdx.x;
    const int col = tid & 63;
    const int oh  = tid >> 6;
    const int rb  = oh * 8;

    const int r3 = p3 >> 3, k3 = p3 & 7;
    const int p2 = (r3 >> 1) * 4 + (k3 >> 1);
    const int c2 = ((r3 & 1) << 1) | (k3 & 1);

    const int nodeA = 5 + p2;
    const int nodeB = 21 + p3;
    const float* FcA = (c2 == 0 ? ftl : c2 == 1 ? ftr : c2 == 2 ? fbl : fbr)
                       + (size_t)nodeA * 1024;
    const float* FcB = (c3 == 0 ? ftl : c3 == 1 ? ftr : c3 == 2 ? fbl : fbr)
                       + (size_t)nodeB * 1024;

    stage_factor_n(fiA, fin + (size_t)nodeA * 1024, scale + (size_t)nodeA * 16, tid, 128);
    stage_factor_n(FA,  FcA, nullptr, tid, 128);
    stage_factor_n(fiB, fin + (size_t)nodeB * 1024, scale + (size_t)nodeB * 16, tid, 128);
    stage_factor_n(FB,  FcB, nullptr, tid, 128);
    {
        const float4* xbase = xin + (size_t)p2 * 16 * 128 + qh * 64;
#pragma unroll
        for (int j = 0; j < 8; j++) {
            int idx = tid + j * 128;
            x_s[idx >> 6][idx & 63] = xbase[(idx >> 6) * 128 + (idx & 63)];
        }
    }
    __syncthreads();

    u64 lp[16];

    {   // latA r-half
        u64 a[8];
#pragma unroll
        for (int rr = 0; rr < 8; rr++) a[rr] = 0ull;
#pragma unroll 4
        for (int i4 = 0; i4 < 16; i4++) {
            ulonglong2 xv = *(const ulonglong2*)&x_s[i4][col];
#pragma unroll
            for (int rr = 0; rr < 8; rr++) {
                ulonglong2 f = *(const ulonglong2*)&fiA[rb + rr][i4 * 4];
                fma2(a[rr], xv.x, f.x);
                fma2(a[rr], xv.y, f.y);
            }
        }
#pragma unroll
        for (int rr = 0; rr < 8; rr++) lat_s[rb + rr][col] = fold2(a[rr]);
    }
    __syncthreads();

#pragma unroll
    for (int r = 0; r < 16; r++) { float v = lat_s[r][col]; lp[r] = pack2(v, v); }
#pragma unroll 4
    for (int oo = 0; oo < 8; oo++) {
        const int o4 = rb + oo;
        ulonglong2 a = *(const ulonglong2*)&x_s[o4][col];
#pragma unroll
        for (int r = 0; r < 16; r++) {
            ulonglong2 f = *(const ulonglong2*)&FA[r][o4 * 4];
            fma2(a.x, lp[r], f.x);
            fma2(a.y, lp[r], f.y);
        }
        *(ulonglong2*)&x_s[o4][col] = a;
    }
    __syncthreads();

    {   // latB r-half
        u64 a[8];
#pragma unroll
        for (int rr = 0; rr < 8; rr++) a[rr] = 0ull;
#pragma unroll 4
        for (int i4 = 0; i4 < 16; i4++) {
            ulonglong2 xv = *(const ulonglong2*)&x_s[i4][col];
#pragma unroll
            for (int rr = 0; rr < 8; rr++) {
                ulonglong2 f = *(const ulonglong2*)&fiB[rb + rr][i4 * 4];
                fma2(a[rr], xv.x, f.x);
                fma2(a[rr], xv.y, f.y);
            }
        }
#pragma unroll
        for (int rr = 0; rr < 8; rr++) lat_s[rb + rr][col] = fold2(a[rr]);
    }
    __syncthreads();

#pragma unroll
    for (int r = 0; r < 16; r++) { float v = lat_s[r][col]; lp[r] = pack2(v, v); }
    const int gr = p3 >> 3, gc = p3 & 7;
    const int cn = (2 * gr + (c3 >> 1)) * 16 + 2 * gc + (c3 & 1);
    float4* op = xout + ((size_t)cn * 16) * 128 + qh * 64 + col;
#pragma unroll 4
    for (int oo = 0; oo < 8; oo++) {
        const int o4 = rb + oo;
        ulonglong2 a = *(const ulonglong2*)&x_s[o4][col];
#pragma unroll
        for (int r = 0; r < 16; r++) {
            ulonglong2 f = *(const ulonglong2*)&FB[r][o4 * 4];
            fma2(a.x, lp[r], f.x);
            fma2(a.y, lp[r], f.y);
        }
        *(ulonglong2*)&op[o4 * 128] = a;
    }
}

// ---------------------------------------------------------------------------
// qt_stack: 256 threads, single pass. grid = 1024 (p4*4+q4).
// threads = g(8: 16-row group) x col(32).
// ---------------------------------------------------------------------------
__global__ __launch_bounds__(256, 2)
void qt_stack(const float4* __restrict__ xin,
              const float* __restrict__ fin, const float* __restrict__ scale,
              const float* __restrict__ head_w, const float* __restrict__ head_b,
              float* __restrict__ lat4o, float* __restrict__ f5xo,
              float* __restrict__ wxo)
{
    __shared__ __align__(16) float FI[128][64];
    __shared__ __align__(16) float4 x_s[16][32];
    __shared__ float hb_s[48];

    const int bid = blockIdx.x;
    const int p4  = bid >> 2;
    const int q4  = bid & 3;
    const int tid = threadIdx.x;
    const int col = tid & 31;
    const int g   = tid >> 5;           // 0..7

    const int gr4 = p4 >> 4, gc4 = p4 & 15;
    const int nodeA = 85 + p4;

    stage_factor_n((float (*)[64])&FI[0], fin + (size_t)nodeA * 1024,
                   scale + (size_t)nodeA * 16, tid, 256);
#pragma unroll
    for (int j = 0; j < 4; j++) {
        const int cnj = (2 * gr4 + (j >> 1)) * 32 + 2 * gc4 + (j & 1);
        const int node = 341 + cnj;
        stage_factor_n((float (*)[64])&FI[16 + 16 * j], fin + (size_t)node * 1024,
                       scale + (size_t)node * 16, tid, 256);
    }
    {
        const float4* w4 = (const float4*)head_w;
        float4* d = (float4*)&FI[80][0];
        for (int i = tid; i < 768; i += 256) d[i] = w4[i];
        if (tid < 48) hb_s[tid] = head_b[tid];
        const float4* xbase = xin + (size_t)p4 * 16 * 128 + q4 * 32;
#pragma unroll
        for (int j = 0; j < 2; j++) {
            int idx = tid + j * 256;
            x_s[idx >> 5][idx & 31] = xbase[(idx >> 5) * 128 + (idx & 31)];
        }
    }
    __syncthreads();

    const int b = q4 * 32 + col;
    const int rbase = g * 16;

    u64 acc[16];
#pragma unroll
    for (int rr = 0; rr < 16; rr++) acc[rr] = 0ull;
#pragma unroll 2
    for (int i4 = 0; i4 < 16; i4++) {
        ulonglong2 xv = *(const ulonglong2*)&x_s[i4][col];
#pragma unroll
        for (int rr = 0; rr < 16; rr++) {
            ulonglong2 f = *(const ulonglong2*)&FI[rbase + rr][i4 * 4];
            fma2(acc[rr], xv.x, f.x);
            fma2(acc[rr], xv.y, f.y);
        }
    }

    if (g == 0) {
        float* dst = lat4o + (size_t)p4 * 16 * 128 + b;
#pragma unroll
        for (int rr = 0; rr < 16; rr++) dst[rr * 128] = fold2(acc[rr]);
    } else if (g <= 4) {
        const int j = g - 1;
        const int cnj = (2 * gr4 + (j >> 1)) * 32 + 2 * gc4 + (j & 1);
        float* dst = f5xo + (size_t)cnj * 16 * 128 + b;
#pragma unroll
        for (int rr = 0; rr < 16; rr++) dst[rr * 128] = fold2(acc[rr]);
    } else {
        const int k0 = (g - 5) * 16;
        float* dst = wxo + ((size_t)p4 * 48 + k0) * 128 + b;
#pragma unroll
        for (int rr = 0; rr < 16; rr++)
            dst[rr * 128] = fold2(acc[rr]) + hb_s[k0 + rr];
    }
}

// ---------------------------------------------------------------------------
// qt_final: one block per cn (1024 blocks), 256 thr = kq(4) x col(64),
// batch-halves looped inside (weights staged ONCE per cn).
// ---------------------------------------------------------------------------
__global__ __launch_bounds__(256, 2)
void qt_final(const float* __restrict__ lat4i, const float* __restrict__ f5xi,
              const float* __restrict__ wxi,
              const float* __restrict__ wf, const float* __restrict__ wfa,
              const float* __restrict__ gg,
              float* __restrict__ out)
{
    __shared__ __align__(16) float g_s[16][16];
    __shared__ __align__(16) float wfa_s[48][16];
    __shared__ __align__(16) float wf5_s[4 * 48][16];

    const int cn  = blockIdx.x;
    const int tid = threadIdx.x;
    const int col = tid & 63;
    const int kq  = tid >> 6;
    const int k0  = kq * 12;

    const int r5 = cn >> 5, c5 = cn & 31;
    const int p4 = (r5 >> 1) * 16 + (c5 >> 1);

    {
        if (tid < 64)
            ((float4*)g_s)[tid] = ((const float4*)(gg + (size_t)cn * 256))[tid];
        const float4* sa = (const float4*)(wfa + (size_t)cn * 768);
        float4* da = (float4*)wfa_s;
        for (int i = tid; i < 192; i += 256) da[i] = sa[i];
        const float4* s5 = (const float4*)(wf + (size_t)cn * 3072);
        float4* d5 = (float4*)wf5_s;
        for (int i = tid; i < 768; i += 256) d5[i] = s5[i];
    }
    __syncthreads();

#pragma unroll 1
    for (int qh = 0; qh < 2; qh++) {
        const int b = qh * 64 + col;

        // lat4 of parent
        float l4[16];
        {
            const float* lp = lat4i + (size_t)p4 * 16 * 128 + b;
#pragma unroll
            for (int r = 0; r < 16; r++) l4[r] = __ldg(&lp[r * 128]);
        }
        u64 latq4[8];
#pragma unroll
        for (int j = 0; j < 8; j++) latq4[j] = pack2(l4[2*j], l4[2*j + 1]);

        // lat5 = F5X + G.lat4
        float l5[16];
        {
            const float* fp = f5xi + (size_t)cn * 16 * 128 + b;
#pragma unroll
            for (int r = 0; r < 16; r++) {
                const ulonglong2* grow = (const ulonglong2*)&g_s[r][0];
                u64 a = 0ull;
#pragma unroll
                for (int j = 0; j < 4; j++) {
                    ulonglong2 f = grow[j];
                    fma2(a, latq4[2*j],     f.x);
                    fma2(a, latq4[2*j + 1], f.y);
                }
                l5[r] = __ldg(&fp[r * 128]) + fold2(a);
            }
        }
        u64 latq5[8];
#pragma unroll
        for (int j = 0; j < 8; j++) latq5[j] = pack2(l5[2*j], l5[2*j + 1]);

        // tk = WX + WFA.lat4 (own 12 k's)
        float tk[12];
        {
            const float* wxp = wxi + ((size_t)p4 * 48 + k0) * 128 + b;
#pragma unroll
            for (int kk = 0; kk < 12; kk++) {
                const ulonglong2* ar = (const ulonglong2*)&wfa_s[k0 + kk][0];
                u64 a = 0ull;
#pragma unroll
                for (int j = 0; j < 4; j++) {
                    ulonglong2 f = ar[j];
                    fma2(a, latq4[2*j],     f.x);
                    fma2(a, latq4[2*j + 1], f.y);
                }
                tk[kk] = __ldg(&wxp[kk * 128]) + fold2(a);
            }
        }

        // 4 children -> pixels
#pragma unroll 1
        for (int c = 0; c < 4; c++) {
            const int cn6 = (2 * r5 + (c >> 1)) * 64 + 2 * c5 + (c & 1);

            float acc[12];
#pragma unroll
            for (int kk = 0; kk < 12; kk++) {
                const ulonglong2* wfr = (const ulonglong2*)&wf5_s[c * 48 + k0 + kk][0];
                u64 a = 0ull;
#pragma unroll
                for (int j = 0; j < 4; j++) {
                    ulonglong2 f = wfr[j];
                    fma2(a, latq5[2*j],     f.x);
                    fma2(a, latq5[2*j + 1], f.y);
                }
                acc[kk] = tk[kk] + fold2(a);
            }

            // k = kq*12 + pc*3 + oc  ->  pr == kq
            const int sr = cn6 >> 6, sc = cn6 & 63;
#pragma unroll
            for (int oc = 0; oc < 3; oc++) {
                float4 v = make_float4(acc[0 + oc], acc[3 + oc], acc[6 + oc], acc[9 + oc]);
                size_t row = (size_t)(b * 3 + oc) * 256 + (sr * 4 + kq);
                *(float4*)(out + row * 256 + sc * 4) = v;
            }
        }
    }
}

// ---------------------------------------------------------------------------
extern "C" void kernel_launch(void* const* d_in, const int* in_sizes, int n_in,
                              void* d_out, int out_size)
{
    const float* x      = (const float*)d_in[0];
    const float* fin    = (const float*)d_in[1];
    const float* ftl    = (const float*)d_in[2];
    const float* ftr    = (const float*)d_in[3];
    const float* fbl    = (const float*)d_in[4];
    const float* fbr    = (const float*)d_in[5];
    const float* scale  = (const float*)d_in[6];
    const float* head_w = (const float*)d_in[7];
    const float* head_b = (const float*)d_in[8];
    float* out = (float*)d_out;

    float4 *x2, *x4;
    float  *wfb, *wfab, *ggb, *lat4b, *f5xb, *wxb;
    cudaGetSymbolAddress((void**)&x2,    g_x2);
    cudaGetSymbolAddress((void**)&x4,    g_x4);
    cudaGetSymbolAddress((void**)&wfb,   g_wf);
    cudaGetSymbolAddress((void**)&wfab,  g_wfa);
    cudaGetSymbolAddress((void**)&ggb,   g_g);
    cudaGetSymbolAddress((void**)&lat4b, g_lat4);
    cudaGetSymbolAddress((void**)&f5xb,  g_f5x);
    cudaGetSymbolAddress((void**)&wxb,   g_wx);

    qt_prep<<<1024, 256>>>(ftl, ftr, fbl, fbr, fin, scale, head_w, wfb, wfab, ggb);
    qt_l01<<<32,  128>>>(x,  x2, fin, ftl, ftr, fbl, fbr, scale);
    qt_l23<<<512, 128>>>(x2, x4, fin, ftl, ftr, fbl, fbr, scale);
    qt_stack<<<1024, 256>>>(x4, fin, scale, head_w, head_b, lat4b, f5xb, wxb);
    qt_final<<<1024, 256>>>(lat4b, f5xb, wxb, wfb, wfab, ggb, out);
}